// round 12
// baseline (speedup 1.0000x reference)
#include <cuda_runtime.h>
#include <cuda_bf16.h>

// p1, p2: [B=2, C=32, D=96, H=96, W=96] fp32
// pool to S=8 (cells 12^3), L = 512 tokens, C = 32 channels.
// loss = (1/(L^2 B)) * sum_b [ ||Ga||F^2 + ||Gb||F^2 - 2||Gx||F^2 ]
// with Ga = Ua^T Ua, Gb = Ub^T Ub, Gx = Ua^T Ub over unit-normalized tokens.
//
// Single fused kernel: pooling blocks take per-chunk tickets; the last
// contributor of each 32-token chunk computes that chunk's partial Grams
// inline (overlapped with remaining pooling). A global done-counter gates
// the final reduction, so the post-pool tail is ~2us.

#define BATCH 2
#define CH    32
#define DIM   96
#define LTOK  512
#define BLK   12
#define EPS   1e-8f
#define LSTR  33
#define NCHUNK 32          // 2 batches x 8 pd x 2 ph-groups
#define CONTRIB 256        // 2 tensors x 32 ch x 4 ph per chunk

// pooled tokens token-major: [tensor(2)][b(2)][l(512)][c(32)]
__device__ float g_pooled[2 * BATCH * LTOK * CH];
// partial Grams: [b(2)][g(3: aa, bb, ab)][i(32)][j(32)]  (zero-init at load;
// re-zeroed by the finalizer each call for graph replay)
__device__ float g_gram[BATCH * 3 * CH * CH];
__device__ unsigned int g_chunk_cnt[NCHUNK];
__device__ unsigned int g_done;

__global__ __launch_bounds__(96, 16)
void fused_kernel(const float* __restrict__ p1,
                  const float* __restrict__ p2,
                  float* __restrict__ out)
{
    const int bid = blockIdx.x;
    const int ph = bid & 7;
    const int pd = (bid >> 3) & 7;
    const int c  = (bid >> 6) & 31;
    const int b  = (bid >> 11) & 1;
    const int t  = bid >> 12;

    const float* __restrict__ in = (t == 0) ? p1 : p2;

    const int tid = threadIdx.x;
    const int f4  = tid % 24;   // w = 4*f4
    const int rs  = tid / 24;   // 0..3 -> d in [3rs, 3rs+3)

    // ---------------- Phase 1: pooling (HBM-bound, 453 MB stream) ----------
    const float* __restrict__ base =
        in + ((size_t)(b * CH + c)) * (DIM * DIM * DIM)
           + (size_t)(pd * BLK + 3 * rs) * (DIM * DIM)
           + (size_t)ph * BLK * DIM
           + f4 * 4;

    float acc = 0.0f;
    #pragma unroll
    for (int d2 = 0; d2 < 3; ++d2) {
        #pragma unroll
        for (int h = 0; h < 12; ++h) {
            const float4 v = __ldcs(reinterpret_cast<const float4*>(
                base + d2 * (DIM * DIM) + h * DIM));
            acc += (v.x + v.y) + (v.z + v.w);
        }
    }

    __shared__ float sh[96];
    sh[tid] = acc;
    __syncthreads();

    if (tid < 8) {
        float s = 0.0f;
        #pragma unroll
        for (int r2 = 0; r2 < 4; ++r2)
            #pragma unroll
            for (int j = 0; j < 3; ++j)
                s += sh[r2 * 24 + tid * 3 + j];
        const int l = pd * 64 + ph * 8 + tid;
        g_pooled[(((size_t)t * BATCH + b) * LTOK + l) * CH + c] =
            s * (1.0f / (BLK * BLK * BLK));
        __threadfence();   // release pooled writes (per writing thread)
    }
    __syncthreads();

    // ---------------- Phase 2: chunk ticket -------------------------------
    const int phg = ph >> 2;
    const int cid = b * 16 + pd * 2 + phg;   // 32 chunks
    const int l0  = pd * 64 + phg * 32;      // first token of chunk

    __shared__ unsigned int s_ticket;
    if (tid == 0) s_ticket = atomicAdd(&g_chunk_cnt[cid], 1u);
    __syncthreads();
    if (s_ticket != CONTRIB - 1) return;     // not the last contributor

    // ---------------- Phase 3: this chunk's partial Grams -----------------
    __threadfence();                          // acquire all contributors

    __shared__ float sh_tok[2 * CH * LSTR];   // [t][c][l], stride 33
    for (int idx = tid; idx < 2 * 32 * CH; idx += 96) {
        const int tt = idx >> 10;
        const int l  = (idx >> 5) & 31;
        const int cc = idx & 31;
        sh_tok[tt * CH * LSTR + cc * LSTR + l] =
            __ldcg(&g_pooled[(((size_t)tt * BATCH + b) * LTOK + l0 + l) * CH + cc]);
    }
    __syncthreads();

    // normalize the 64 token columns (eps never binds for this data;
    // fmaxf keeps exact reference semantics in the degenerate case)
    if (tid < 64) {
        const int tt = tid >> 5;
        const int l  = tid & 31;
        float* col = sh_tok + tt * CH * LSTR + l;
        float s = 0.0f;
        #pragma unroll
        for (int cc = 0; cc < CH; ++cc) {
            const float v = col[cc * LSTR];
            s += v * v;
        }
        const float r = 1.0f / sqrtf(fmaxf(s, EPS));
        #pragma unroll
        for (int cc = 0; cc < CH; ++cc)
            col[cc * LSTR] *= r;
    }
    __syncthreads();

    // 3 warps = 3 Grams (aa, bb, ab); lane = output row i (channel),
    // 8-column register groups; Q reads are warp-broadcast LDS.
    {
        const int g = tid >> 5;   // 0..2
        const int i = tid & 31;
        const float* __restrict__ P = sh_tok + ((g == 1) ? CH * LSTR : 0);
        const float* __restrict__ Q = sh_tok + ((g == 0) ? 0 : CH * LSTR);
        float* __restrict__ dst = g_gram + (((b * 3 + g) << 10) + (i << 5));

        #pragma unroll
        for (int jg = 0; jg < 4; ++jg) {
            float a0 = 0, a1 = 0, a2 = 0, a3 = 0, a4 = 0, a5 = 0, a6 = 0, a7 = 0;
            #pragma unroll
            for (int l = 0; l < 32; ++l) {
                const float p = P[i * LSTR + l];
                const float* q = Q + (jg * 8) * LSTR + l;
                a0 += p * q[0 * LSTR];  a1 += p * q[1 * LSTR];
                a2 += p * q[2 * LSTR];  a3 += p * q[3 * LSTR];
                a4 += p * q[4 * LSTR];  a5 += p * q[5 * LSTR];
                a6 += p * q[6 * LSTR];  a7 += p * q[7 * LSTR];
            }
            atomicAdd(&dst[jg * 8 + 0], a0);  atomicAdd(&dst[jg * 8 + 1], a1);
            atomicAdd(&dst[jg * 8 + 2], a2);  atomicAdd(&dst[jg * 8 + 3], a3);
            atomicAdd(&dst[jg * 8 + 4], a4);  atomicAdd(&dst[jg * 8 + 5], a5);
            atomicAdd(&dst[jg * 8 + 6], a6);  atomicAdd(&dst[jg * 8 + 7], a7);
        }
    }

    // ---------------- Phase 4: done ticket + finalize ----------------------
    __syncthreads();
    if (tid == 0) {
        g_chunk_cnt[cid] = 0u;               // reset for next replay
        __threadfence();                      // release gram atomics
        s_ticket = atomicAdd(&g_done, 1u);
    }
    __syncthreads();
    if (s_ticket != NCHUNK - 1) return;      // not the last chunk

    __threadfence();                          // acquire all gram updates

    float local = 0.0f;
    for (int i2 = tid; i2 < BATCH * 3 * CH * CH; i2 += 96) {
        const int gg = (i2 >> 10) % 3;
        const float v = __ldcg(&g_gram[i2]);
        local += ((gg == 2) ? -2.0f : 1.0f) * v * v;
    }
    #pragma unroll
    for (int off = 16; off > 0; off >>= 1)
        local += __shfl_xor_sync(0xFFFFFFFFu, local, off);

    __shared__ float wsum[3];
    if ((tid & 31) == 0) wsum[tid >> 5] = local;
    __syncthreads();
    if (tid == 0) {
        const float s = wsum[0] + wsum[1] + wsum[2];
        out[0] = s * (1.0f / ((float)LTOK * (float)LTOK * (float)BATCH));
        g_done = 0u;                          // reset for next replay
    }
    __syncthreads();                          // reads done before re-zeroing
    for (int i2 = tid; i2 < BATCH * 3 * CH * CH; i2 += 96)
        g_gram[i2] = 0.0f;
}

// ---------------------------------------------------------------------------
extern "C" void kernel_launch(void* const* d_in, const int* in_sizes, int n_in,
                              void* d_out, int out_size)
{
    const float* p1 = (const float*)d_in[0];
    const float* p2 = (const float*)d_in[1];
    float* out = (float*)d_out;

    fused_kernel<<<8192, 96>>>(p1, p2, out);  // 2*2*32*8*8 blocks
}

// round 13
// speedup vs baseline: 1.1932x; 1.1932x over previous
#include <cuda_runtime.h>
#include <cuda_bf16.h>

// p1, p2: [B=2, C=32, D=96, H=96, W=96] fp32
// pool to S=8 (cells 12^3), L = 512 tokens, C = 32 channels.
// loss = (1/(L^2 B)) * sum_b [ ||Ga||F^2 + ||Gb||F^2 - 2||Gx||F^2 ]
// with Ga = Ua^T Ua, Gb = Ub^T Ub, Gx = Ua^T Ub over unit-normalized tokens.

#define BATCH 2
#define CH    32
#define DIM   96
#define LTOK  512
#define BLK   12
#define EPS   1e-8f

// pooled tokens token-major: [tensor(2)][b(2)][l(512)][c(32)]
__device__ float g_pooled[2 * BATCH * LTOK * CH];
// partial Grams: [b(2)][g(3: aa, bb, ab)][i(32)][j(32)]
__device__ float g_gram[BATCH * 3 * CH * CH];
__device__ unsigned int g_cnt;

// ---------------------------------------------------------------------------
// Kernel 1: pooling (identical to the proven 64.6us version).
// One block per (tensor, b, c, pd, ph). 96 threads: f4 = tid%24 (float4
// along w), rs = tid/24 -> contiguous d chunk; all 36 loads are affine
// immediate offsets from one base (front-batched LDG.128, streaming hint).
// Block 0 zeroes the Gram accumulator + counter for this replay.
// ---------------------------------------------------------------------------
__global__ __launch_bounds__(96) void pool_kernel(const float* __restrict__ p1,
                                                  const float* __restrict__ p2)
{
    const int bid = blockIdx.x;
    if (bid == 0) {
        for (int i = threadIdx.x; i < BATCH * 3 * CH * CH; i += 96)
            g_gram[i] = 0.0f;
        if (threadIdx.x == 0) g_cnt = 0u;
    }

    const int ph = bid & 7;
    const int pd = (bid >> 3) & 7;
    const int c  = (bid >> 6) & 31;
    const int b  = (bid >> 11) & 1;
    const int t  = bid >> 12;

    const float* __restrict__ in = (t == 0) ? p1 : p2;

    const int tid = threadIdx.x;
    const int f4  = tid % 24;   // w = 4*f4
    const int rs  = tid / 24;   // 0..3 -> d in [3rs, 3rs+3)

    const float* __restrict__ base =
        in + ((size_t)(b * CH + c)) * (DIM * DIM * DIM)
           + (size_t)(pd * BLK + 3 * rs) * (DIM * DIM)
           + (size_t)ph * BLK * DIM
           + f4 * 4;

    float acc = 0.0f;
    #pragma unroll
    for (int d2 = 0; d2 < 3; ++d2) {
        #pragma unroll
        for (int h = 0; h < 12; ++h) {
            const float4 v = __ldcs(reinterpret_cast<const float4*>(
                base + d2 * (DIM * DIM) + h * DIM));
            acc += (v.x + v.y) + (v.z + v.w);
        }
    }

    __shared__ float sh[96];
    sh[tid] = acc;
    __syncthreads();

    if (tid < 8) {
        float s = 0.0f;
        #pragma unroll
        for (int r2 = 0; r2 < 4; ++r2)
            #pragma unroll
            for (int j = 0; j < 3; ++j)
                s += sh[r2 * 24 + tid * 3 + j];
        const int l = pd * 64 + ph * 8 + tid;
        g_pooled[(((size_t)t * BATCH + b) * LTOK + l) * CH + c] =
            s * (1.0f / (BLK * BLK * BLK));
    }
}

// ---------------------------------------------------------------------------
// Kernel 2: Gram accumulation + fused finalize (latency-tightened).
// 32 blocks = 2 batches x 16 l-chunks (32 tokens each), 256 threads.
// Load+normalize fused: 4 threads per token, float4 LDG, quad shfl reduce,
// rsqrtf, normalized write to channel-major shared (stride 33). Gram loop
// fuses aa+ab (shared P loads). Last block reduces +/-||G||^2 via float4.
// ---------------------------------------------------------------------------
#define LSTR 33
#define SIM_BLOCKS 32

__global__ __launch_bounds__(256) void sim_kernel(float* __restrict__ out)
{
    __shared__ float sh[2 * CH * LSTR];   // [t][c][l] : 8.4 KB
    __shared__ float wsum[8];
    __shared__ int is_last;

    const int b     = blockIdx.x >> 4;    // 0..1
    const int chunk = blockIdx.x & 15;    // 0..15
    const int l0    = chunk * 32;
    const int tid   = threadIdx.x;

    // ---- fused load + normalize: 64 token-columns, 4 threads each --------
    {
        const int tok = tid >> 2;          // 0..63
        const int sub = tid & 3;           // 0..3 -> channels [8*sub, 8*sub+8)
        const int tt  = tok >> 5;          // tensor
        const int l   = tok & 31;

        const float* __restrict__ src =
            g_pooled + (((size_t)tt * BATCH + b) * LTOK + l0 + l) * CH + sub * 8;
        const float4 v0 = __ldcg(reinterpret_cast<const float4*>(src));
        const float4 v1 = __ldcg(reinterpret_cast<const float4*>(src + 4));

        float s = v0.x * v0.x + v0.y * v0.y + v0.z * v0.z + v0.w * v0.w
                + v1.x * v1.x + v1.y * v1.y + v1.z * v1.z + v1.w * v1.w;
        s += __shfl_xor_sync(0xFFFFFFFFu, s, 1);
        s += __shfl_xor_sync(0xFFFFFFFFu, s, 2);
        const float r = rsqrtf(fmaxf(s, EPS));

        float* __restrict__ dst = sh + tt * CH * LSTR + (sub * 8) * LSTR + l;
        dst[0 * LSTR] = v0.x * r;  dst[1 * LSTR] = v0.y * r;
        dst[2 * LSTR] = v0.z * r;  dst[3 * LSTR] = v0.w * r;
        dst[4 * LSTR] = v1.x * r;  dst[5 * LSTR] = v1.y * r;
        dst[6 * LSTR] = v1.z * r;  dst[7 * LSTR] = v1.w * r;
    }
    __syncthreads();

    // ---- 2x2 register-tiled Grams over this chunk's 32 l's ---------------
    const int tj = tid & 15;
    const int ti = tid >> 4;
    const float* __restrict__ A = sh;
    const float* __restrict__ B = sh + CH * LSTR;
    float* __restrict__ dstb = g_gram + ((size_t)b * 3) * (CH * CH);

    // fused: Gaa (A,A) and Gab (A,B) share P = A row loads
    {
        float s00 = 0, s01 = 0, s10 = 0, s11 = 0;   // aa
        float x00 = 0, x01 = 0, x10 = 0, x11 = 0;   // ab
        #pragma unroll 8
        for (int l = 0; l < 32; ++l) {
            const float p0 = A[(2 * ti)     * LSTR + l];
            const float p1 = A[(2 * ti + 1) * LSTR + l];
            const float qa0 = A[(2 * tj)     * LSTR + l];
            const float qa1 = A[(2 * tj + 1) * LSTR + l];
            const float qb0 = B[(2 * tj)     * LSTR + l];
            const float qb1 = B[(2 * tj + 1) * LSTR + l];
            s00 += p0 * qa0;  s01 += p0 * qa1;
            s10 += p1 * qa0;  s11 += p1 * qa1;
            x00 += p0 * qb0;  x01 += p0 * qb1;
            x10 += p1 * qb0;  x11 += p1 * qb1;
        }
        float* d0 = dstb;                 // aa
        float* d2 = dstb + 2 * CH * CH;   // ab
        atomicAdd(&d0[(2 * ti)     * CH + 2 * tj],     s00);
        atomicAdd(&d0[(2 * ti)     * CH + 2 * tj + 1], s01);
        atomicAdd(&d0[(2 * ti + 1) * CH + 2 * tj],     s10);
        atomicAdd(&d0[(2 * ti + 1) * CH + 2 * tj + 1], s11);
        atomicAdd(&d2[(2 * ti)     * CH + 2 * tj],     x00);
        atomicAdd(&d2[(2 * ti)     * CH + 2 * tj + 1], x01);
        atomicAdd(&d2[(2 * ti + 1) * CH + 2 * tj],     x10);
        atomicAdd(&d2[(2 * ti + 1) * CH + 2 * tj + 1], x11);
    }
    // Gbb (B,B)
    {
        float s00 = 0, s01 = 0, s10 = 0, s11 = 0;
        #pragma unroll 8
        for (int l = 0; l < 32; ++l) {
            const float p0 = B[(2 * ti)     * LSTR + l];
            const float p1 = B[(2 * ti + 1) * LSTR + l];
            const float q0 = B[(2 * tj)     * LSTR + l];
            const float q1 = B[(2 * tj + 1) * LSTR + l];
            s00 += p0 * q0;  s01 += p0 * q1;
            s10 += p1 * q0;  s11 += p1 * q1;
        }
        float* d1 = dstb + CH * CH;
        atomicAdd(&d1[(2 * ti)     * CH + 2 * tj],     s00);
        atomicAdd(&d1[(2 * ti)     * CH + 2 * tj + 1], s01);
        atomicAdd(&d1[(2 * ti + 1) * CH + 2 * tj],     s10);
        atomicAdd(&d1[(2 * ti + 1) * CH + 2 * tj + 1], s11);
    }

    // ---- completion counter -> last block finalizes -----------------------
    __threadfence();
    __syncthreads();
    if (tid == 0) {
        const unsigned int old = atomicAdd(&g_cnt, 1u);
        is_last = (old == SIM_BLOCKS - 1) ? 1 : 0;
    }
    __syncthreads();
    if (!is_last) return;

    __threadfence();   // acquire all gram atomics

    // loss = sum_b ( ||Gaa||^2 + ||Gbb||^2 - 2||Gab||^2 ) / (L^2 * B)
    float local = 0.0f;
    const float4* __restrict__ gv = reinterpret_cast<const float4*>(g_gram);
    for (int i4 = tid; i4 < (BATCH * 3 * CH * CH) / 4; i4 += 256) {
        const int g = (i4 >> 8) % 3;           // 256 float4 per gram
        const float w = (g == 2) ? -2.0f : 1.0f;
        const float4 v = __ldcg(&gv[i4]);
        local += w * (v.x * v.x + v.y * v.y + v.z * v.z + v.w * v.w);
    }
    #pragma unroll
    for (int off = 16; off > 0; off >>= 1)
        local += __shfl_xor_sync(0xFFFFFFFFu, local, off);
    if ((tid & 31) == 0) wsum[tid >> 5] = local;
    __syncthreads();
    if (tid == 0) {
        float s = 0.0f;
        #pragma unroll
        for (int i = 0; i < 8; ++i) s += wsum[i];
        out[0] = s * (1.0f / ((float)LTOK * (float)LTOK * (float)BATCH));
    }
}

// ---------------------------------------------------------------------------
extern "C" void kernel_launch(void* const* d_in, const int* in_sizes, int n_in,
                              void* d_out, int out_size)
{
    const float* p1 = (const float*)d_in[0];
    const float* p2 = (const float*)d_in[1];
    float* out = (float*)d_out;

    pool_kernel<<<8192, 96>>>(p1, p2);   // 2*2*32*8*8 blocks
    sim_kernel<<<SIM_BLOCKS, 256>>>(out);
}